// round 6
// baseline (speedup 1.0000x reference)
#include <cuda_runtime.h>
#include <cuda_bf16.h>

// Problem constants (fixed shapes per reference)
#define N1 8
#define N2 8
#define PN 1024
#define DD 768
#define PHH 32
#define PWW 32
#define HH 512
#define WW 512

#define FLT_BIG 3.402823466e38f

// -------- scratch (static device globals; no allocations allowed) ----------
__device__ __align__(256) __nv_bfloat16 g_fnh[N1 * PN * DD];  // normalized feats (bf16)
__device__ __align__(256) __nv_bfloat16 g_gnh[N2 * PN * DD];  // normalized nfeats (bf16)
__device__ float    g_fa2[N1 * PN];            // sum(f^2) after normalization (fp32)
__device__ float    g_gb2[N2 * PN];            // sum(g^2) after normalization (fp32)
__device__ unsigned g_minenc[N1 * N2 * PN];    // order-encoded min d2 over q
__device__ float    g_spatch[N1 * N2 * PN];    // scores_patch
__device__ float    g_maxp[N1 * N2];           // max over p of scores_patch
__device__ float    g_sp[N1 * PN];             // mean over m of scores_patch

// ---------------- helpers ----------------
// Order-preserving float<->uint map (monotone increasing)
__device__ __forceinline__ unsigned enc_f(float f) {
    unsigned u = __float_as_uint(f);
    return (u & 0x80000000u) ? ~u : (u | 0x80000000u);
}
__device__ __forceinline__ float dec_f(unsigned e) {
    unsigned u = (e & 0x80000000u) ? (e ^ 0x80000000u) : ~e;
    return __uint_as_float(u);
}

__device__ __forceinline__ void mma_bf16(float& c0, float& c1, float& c2, float& c3,
                                         unsigned a0, unsigned a1, unsigned a2, unsigned a3,
                                         unsigned b0, unsigned b1) {
    asm volatile(
        "mma.sync.aligned.m16n8k16.row.col.f32.bf16.bf16.f32 "
        "{%0,%1,%2,%3}, {%4,%5,%6,%7}, {%8,%9}, {%0,%1,%2,%3};\n"
        : "+f"(c0), "+f"(c1), "+f"(c2), "+f"(c3)
        : "r"(a0), "r"(a1), "r"(a2), "r"(a3), "r"(b0), "r"(b1));
}

// ---------------- kernel 1: row-normalize -> bf16 + sum-of-squares ----------
// which==0 -> g_fnh/g_fa2, which==1 -> g_gnh/g_gb2. One block per row.
__global__ void normalize_kernel(const float* __restrict__ in, int which) {
    int row = blockIdx.x;
    const float* x = in + (size_t)row * DD;
    __nv_bfloat16* y = (which ? g_gnh : g_fnh) + (size_t)row * DD;
    float* sq = (which ? g_gb2 : g_fa2);

    __shared__ float red[256];
    int t = threadIdx.x;

    float s = 0.f;
    for (int i = t; i < DD; i += 256) { float v = x[i]; s += v * v; }
    red[t] = s; __syncthreads();
    for (int o = 128; o > 0; o >>= 1) { if (t < o) red[t] += red[t + o]; __syncthreads(); }
    float nrm = sqrtf(red[0]);
    __syncthreads();

    float s2 = 0.f;
    for (int i = t; i < DD; i += 256) {
        float v = x[i] / nrm;        // match reference: divide by norm
        y[i] = __float2bfloat16_rn(v);
        s2 += v * v;                 // fa2/gb2 from fp32 normalized values
    }
    red[t] = s2; __syncthreads();
    for (int o = 128; o > 0; o >>= 1) { if (t < o) red[t] += red[t + o]; __syncthreads(); }
    if (t == 0) sq[row] = red[0];
}

// ---------------- kernel 2: init min buffer ----------------
__global__ void init_min_kernel() {
    int i = blockIdx.x * blockDim.x + threadIdx.x;
    if (i < N1 * N2 * PN) g_minenc[i] = 0xFFFFFFFFu;
}

// ---------------- kernel 3: fused bf16 MMA GEMM + min-over-q epilogue -------
// For each (n,m): C[p,q] = f_n[p] . g_m[q]; track min_q (gb2[q] - 2*C) per p.
// 128x128 block tile, BK=32, 8 warps (2 m-warps x 4 n-warps), warp = 64x32
// via 4x4 m16n8k16 bf16 mma.sync tiles. K-major smem, rows padded to 40
// elements (conflict-free fragment LDS: bank = (20*row + qd + kk/2) mod 32,
// all 32 distinct within a warp). Register-prefetch global loads.
#define BM 128
#define BN 128
#define BK 32
#define SPAD 40   // smem row stride in bf16 elems (32 data + 8 pad)

__global__ __launch_bounds__(256) void gemm_min_kernel() {
    const int nIdx = blockIdx.z >> 3;
    const int mIdx = blockIdx.z & 7;
    const int p0 = blockIdx.y * BM;
    const int q0 = blockIdx.x * BN;

    const __nv_bfloat16* __restrict__ Fp = g_fnh + ((size_t)nIdx * PN + p0) * DD;
    const __nv_bfloat16* __restrict__ Gp = g_gnh + ((size_t)mIdx * PN + q0) * DD;

    __shared__ __align__(16) __nv_bfloat16 As[BM][SPAD];
    __shared__ __align__(16) __nv_bfloat16 Bs[BN][SPAD];

    const int t    = threadIdx.x;
    const int lane = t & 31;
    const int warp = t >> 5;
    const int wm   = warp >> 2;   // 0..1 -> 64 rows each
    const int wn   = warp & 3;    // 0..3 -> 32 cols each
    const int grp  = lane >> 2;   // 0..7
    const int qd   = lane & 3;    // 0..3

    // loader mapping: 2 threads per row, each loads 16 bf16 (2 x uint4)
    const int lrow = t >> 1;          // 0..127
    const int lcol = (t & 1) * 16;    // 0 or 16

    const __nv_bfloat16* fptr = Fp + (size_t)lrow * DD + lcol;
    const __nv_bfloat16* gptr = Gp + (size_t)lrow * DD + lcol;

    float acc[4][4][4];
#pragma unroll
    for (int i = 0; i < 4; i++)
#pragma unroll
        for (int j = 0; j < 4; j++)
#pragma unroll
            for (int c = 0; c < 4; c++) acc[i][j][c] = 0.f;

    // prologue: tile 0 -> smem
    uint4 pa0 = *(const uint4*)(fptr);
    uint4 pa1 = *(const uint4*)(fptr + 8);
    uint4 pb0 = *(const uint4*)(gptr);
    uint4 pb1 = *(const uint4*)(gptr + 8);
    *(uint4*)&As[lrow][lcol]     = pa0;
    *(uint4*)&As[lrow][lcol + 8] = pa1;
    *(uint4*)&Bs[lrow][lcol]     = pb0;
    *(uint4*)&Bs[lrow][lcol + 8] = pb1;
    __syncthreads();

    for (int k0 = 0; k0 < DD; k0 += BK) {
        const bool has_next = (k0 + BK) < DD;
        if (has_next) {  // prefetch next tile into regs (overlaps mma below)
            pa0 = *(const uint4*)(fptr + k0 + BK);
            pa1 = *(const uint4*)(fptr + k0 + BK + 8);
            pb0 = *(const uint4*)(gptr + k0 + BK);
            pb1 = *(const uint4*)(gptr + k0 + BK + 8);
        }

#pragma unroll
        for (int kk = 0; kk < BK; kk += 16) {
            // B fragments: 4 n-tiles (col-major k16n8)
            unsigned bf[4][2];
#pragma unroll
            for (int j = 0; j < 4; j++) {
                const int col = wn * 32 + j * 8 + grp;  // q row in Bs
                bf[j][0] = *(const unsigned*)&Bs[col][kk + qd * 2];
                bf[j][1] = *(const unsigned*)&Bs[col][kk + qd * 2 + 8];
            }
#pragma unroll
            for (int i = 0; i < 4; i++) {
                const int row = wm * 64 + i * 16 + grp;
                const unsigned a0 = *(const unsigned*)&As[row][kk + qd * 2];
                const unsigned a1 = *(const unsigned*)&As[row + 8][kk + qd * 2];
                const unsigned a2 = *(const unsigned*)&As[row][kk + qd * 2 + 8];
                const unsigned a3 = *(const unsigned*)&As[row + 8][kk + qd * 2 + 8];
#pragma unroll
                for (int j = 0; j < 4; j++)
                    mma_bf16(acc[i][j][0], acc[i][j][1], acc[i][j][2], acc[i][j][3],
                             a0, a1, a2, a3, bf[j][0], bf[j][1]);
            }
        }
        __syncthreads();

        if (has_next) {
            *(uint4*)&As[lrow][lcol]     = pa0;
            *(uint4*)&As[lrow][lcol + 8] = pa1;
            *(uint4*)&Bs[lrow][lcol]     = pb0;
            *(uint4*)&Bs[lrow][lcol + 8] = pb1;
            __syncthreads();
        }
    }

    // ---------------- epilogue: min over q of (gb2[q] - 2*C[p,q]) ----------
    // gb2 for this thread's 8 columns (4 n-tiles x 2 cols)
    const float* __restrict__ gb2p = g_gb2 + mIdx * PN + q0;
    float gbv[4][2];
#pragma unroll
    for (int j = 0; j < 4; j++) {
        const int c = wn * 32 + j * 8 + qd * 2;
        gbv[j][0] = gb2p[c];
        gbv[j][1] = gb2p[c + 1];
    }

    __syncthreads();  // done with As/Bs; reuse As as reduction buffer
    float (*red)[4] = (float (*)[4]) & As[0][0];  // [128 rows][4 wn]

#pragma unroll
    for (int i = 0; i < 4; i++) {
        float mn_lo = FLT_BIG, mn_hi = FLT_BIG;
#pragma unroll
        for (int j = 0; j < 4; j++) {
            mn_lo = fminf(mn_lo, gbv[j][0] - 2.f * acc[i][j][0]);
            mn_lo = fminf(mn_lo, gbv[j][1] - 2.f * acc[i][j][1]);
            mn_hi = fminf(mn_hi, gbv[j][0] - 2.f * acc[i][j][2]);
            mn_hi = fminf(mn_hi, gbv[j][1] - 2.f * acc[i][j][3]);
        }
        // reduce across the 4 lanes sharing a row (qd = 0..3)
#pragma unroll
        for (int o = 1; o < 4; o <<= 1) {
            mn_lo = fminf(mn_lo, __shfl_xor_sync(0xFFFFFFFFu, mn_lo, o));
            mn_hi = fminf(mn_hi, __shfl_xor_sync(0xFFFFFFFFu, mn_hi, o));
        }
        if (qd == 0) {
            red[wm * 64 + i * 16 + grp][wn]     = mn_lo;
            red[wm * 64 + i * 16 + grp + 8][wn] = mn_hi;
        }
    }
    __syncthreads();

    if (t < BM) {
        float mn = fminf(fminf(red[t][0], red[t][1]), fminf(red[t][2], red[t][3]));
        const float d2 = g_fa2[nIdx * PN + p0 + t] + mn;
        atomicMin(&g_minenc[((nIdx << 3) + mIdx) * PN + p0 + t], enc_f(d2));
    }
}

// ---------------- kernel 4: scores_patch + max over p ----------------
__global__ void patch_kernel() {
    const int nm = blockIdx.x;  // n*8+m
    __shared__ float red[256];
    const int t = threadIdx.x;
    float mx = 0.f;
    for (int p = t; p < PN; p += 256) {
        const float d2 = dec_f(g_minenc[nm * PN + p]);
        const float s = 0.5f * sqrtf(fmaxf(d2, 0.f));
        g_spatch[nm * PN + p] = s;
        mx = fmaxf(mx, s);
    }
    red[t] = mx; __syncthreads();
    for (int o = 128; o > 0; o >>= 1) { if (t < o) red[t] = fmaxf(red[t], red[t + o]); __syncthreads(); }
    if (t == 0) g_maxp[nm] = red[0];
}

// ---------------- kernel 5: mean over m (sp) + scores ----------------
__global__ void reduce_kernel(float* __restrict__ out) {
    const int idx = blockIdx.x * blockDim.x + threadIdx.x;  // 0..N1*PN-1
    if (idx >= N1 * PN) return;
    const int n = idx / PN;
    const int p = idx - n * PN;
    float s = 0.f;
#pragma unroll
    for (int m = 0; m < N2; m++) s += g_spatch[((n << 3) + m) * PN + p];
    g_sp[idx] = s * (1.0f / N2);
    if (idx < N1) {
        float sc = 0.f;
#pragma unroll
        for (int m = 0; m < N2; m++) sc += g_maxp[(idx << 3) + m];
        out[idx] = sc * (1.0f / N2);
    }
}

// ---------------- kernel 6: bilinear resize 32x32 -> 512x512 ----------------
__global__ void bilinear_kernel(float* __restrict__ out) {
    const int gid = blockIdx.x * blockDim.x + threadIdx.x;
    if (gid >= N1 * HH * WW) return;
    const int x = gid % WW;
    const int y = (gid / WW) % HH;
    const int n = gid / (WW * HH);

    const float sy = (y + 0.5f) * ((float)PHH / (float)HH) - 0.5f;
    const float sx = (x + 0.5f) * ((float)PWW / (float)WW) - 0.5f;
    const float y0f = floorf(sy), x0f = floorf(sx);
    const float wy = sy - y0f, wx = sx - x0f;
    const int y0 = min(max((int)y0f, 0), PHH - 1);
    const int y1 = min(max((int)y0f + 1, 0), PHH - 1);
    const int x0 = min(max((int)x0f, 0), PWW - 1);
    const int x1 = min(max((int)x0f + 1, 0), PWW - 1);

    const float* sp = g_sp + n * PN;
    const float v00 = sp[y0 * PWW + x0];
    const float v01 = sp[y0 * PWW + x1];
    const float v10 = sp[y1 * PWW + x0];
    const float v11 = sp[y1 * PWW + x1];
    const float top = v00 * (1.f - wx) + v01 * wx;
    const float bot = v10 * (1.f - wx) + v11 * wx;
    out[N1 + gid] = top * (1.f - wy) + bot * wy;
}

// ---------------- launch ----------------
extern "C" void kernel_launch(void* const* d_in, const int* in_sizes, int n_in,
                              void* d_out, int out_size) {
    const float* feats  = (const float*)d_in[0];
    const float* nfeats = (const float*)d_in[1];
    float* out = (float*)d_out;
    (void)in_sizes; (void)n_in; (void)out_size;

    normalize_kernel<<<N1 * PN, 256>>>(feats, 0);
    normalize_kernel<<<N2 * PN, 256>>>(nfeats, 1);
    init_min_kernel<<<(N1 * N2 * PN + 255) / 256, 256>>>();
    gemm_min_kernel<<<dim3(PN / BN, PN / BM, N1 * N2), 256>>>();
    patch_kernel<<<N1 * N2, 256>>>();
    reduce_kernel<<<(N1 * PN + 255) / 256, 256>>>(out);
    bilinear_kernel<<<(N1 * HH * WW + 255) / 256, 256>>>(out);
}